// round 11
// baseline (speedup 1.0000x reference)
#include <cuda_runtime.h>
#include <cuda_bf16.h>
#include <stdint.h>

// ===================== problem constants =====================
#define D_IN 256
#define D_G  512
#define VBS  128

// ===================== SMEM layout (bytes) ===================
#define OFF_SCALE 0            // f32[512]
#define OFF_SHIFT 2048         // f32[512]
#define OFF_PSUM  4096         // f32[2][512]
#define OFF_PSQ   12288        // f32[2][512]
#define OFF_AHI   20480        // bf16[64][72] = 9216 B
#define OFF_ALO   29696        // bf16[64][72] = 9216 B
#define OFF_CBUF  38912        // f32[64][520] = 133120 B
#define DYN_SMEM  172032
#define CPITCH    520          // f32 elements per C row (512 + 8 pad)

// ===================== W fragment scratch ====================
// Fragment-order layout for mma.sync m16n8k16 operand B (.col):
//   u32 index = ((nt*16 + kt)*32 + lane)*2 + r
//   value     = pack(bf16 W[n][k], bf16 W[n][k+1])
//   n = nt*8 + lane/4 ; k = kt*16 + r*8 + (lane&3)*2
__device__ uint32_t g_Bhi[64 * 16 * 32 * 2];
__device__ uint32_t g_Blo[64 * 16 * 32 * 2];

__global__ void prep_w_kernel(const float* __restrict__ W) {
    int idx  = blockIdx.x * 256 + threadIdx.x;   // 0 .. 65535
    int r    = idx & 1;
    int lane = (idx >> 1) & 31;
    int kt   = (idx >> 6) & 15;
    int nt   = idx >> 10;
    int n = nt * 8 + (lane >> 2);
    int k = kt * 16 + r * 8 + (lane & 3) * 2;
    float w0 = W[n * D_IN + k];
    float w1 = W[n * D_IN + k + 1];
    __nv_bfloat16 h0 = __float2bfloat16(w0);
    __nv_bfloat16 h1 = __float2bfloat16(w1);
    __nv_bfloat16 l0 = __float2bfloat16(w0 - __bfloat162float(h0));
    __nv_bfloat16 l1 = __float2bfloat16(w1 - __bfloat162float(h1));
    union { __nv_bfloat16 h[2]; uint32_t u; } H, L;
    H.h[0] = h0; H.h[1] = h1;
    L.h[0] = l0; L.h[1] = l1;
    g_Bhi[idx] = H.u;
    g_Blo[idx] = L.u;
}

// ===================== device helpers ========================
static __device__ __forceinline__ uint32_t smem_u32(const void* p) {
    uint32_t a;
    asm("{ .reg .u64 t; cvta.to.shared.u64 t, %1; cvt.u32.u64 %0, t; }"
        : "=r"(a) : "l"(p));
    return a;
}

static __device__ __forceinline__ void mma16816(float d[4],
                                                uint32_t a0, uint32_t a1,
                                                uint32_t a2, uint32_t a3,
                                                uint32_t b0, uint32_t b1) {
    asm volatile(
        "mma.sync.aligned.m16n8k16.row.col.f32.bf16.bf16.f32 "
        "{%0,%1,%2,%3}, {%4,%5,%6,%7}, {%8,%9}, {%0,%1,%2,%3};"
        : "+f"(d[0]), "+f"(d[1]), "+f"(d[2]), "+f"(d[3])
        : "r"(a0), "r"(a1), "r"(a2), "r"(a3), "r"(b0), "r"(b1));
}

// GEMM for one 64-row half: acc[mt][nt][4] covers warp tile rows rg*32+..,
// cols cg*64+.. ; 3x bf16 split; A staged per 64-K chunk.
static __device__ __forceinline__ void gemm_half(
    const float* __restrict__ feat, int grow0, char* smem, uint32_t sb,
    int tid, int w, int lane, float acc[2][8][4])
{
    const int rg = w >> 3, cg = w & 7;
    const uint32_t a_row_off = (uint32_t)((rg * 32 + (lane & 15)) * 144 + (lane >> 4) * 16);
    const int bwarp = cg * 4096;   // (cg*8)*16*32

    #pragma unroll 1
    for (int kc = 0; kc < 4; kc++) {
        __syncthreads();                      // prev chunk's A reads done
        {   // stage A chunk [64 rows][64 k]: fp32 -> bf16 hi/lo, pitch 72
            int r = tid >> 3, seg = tid & 7;
            const float4* p =
                (const float4*)(feat + (size_t)(grow0 + r) * D_IN + kc * 64 + seg * 8);
            float4 fa = p[0], fb = p[1];
            float f[8] = {fa.x, fa.y, fa.z, fa.w, fb.x, fb.y, fb.z, fb.w};
            union { __nv_bfloat16 h[8]; uint4 u; } H, L;
            #pragma unroll
            for (int e = 0; e < 8; e++) {
                H.h[e] = __float2bfloat16(f[e]);
                L.h[e] = __float2bfloat16(f[e] - __bfloat162float(H.h[e]));
            }
            uint32_t off = (uint32_t)(r * 144 + seg * 16);
            *(uint4*)(smem + OFF_AHI + off) = H.u;
            *(uint4*)(smem + OFF_ALO + off) = L.u;
        }
        __syncthreads();

        #pragma unroll
        for (int pass = 0; pass < 3; pass++) {
            const uint32_t abase = sb + (pass == 2 ? OFF_ALO : OFF_AHI) + a_row_off;
            const uint2* bp = (const uint2*)(pass == 1 ? g_Blo : g_Bhi);
            #pragma unroll
            for (int ks = 0; ks < 4; ks++) {
                const int kt = kc * 4 + ks;
                uint2 bb[8];
                #pragma unroll
                for (int nt = 0; nt < 8; nt++)
                    bb[nt] = bp[bwarp + nt * 512 + kt * 32 + lane];
                #pragma unroll
                for (int mt = 0; mt < 2; mt++) {
                    uint32_t a0, a1, a2, a3;
                    uint32_t addr = abase + (uint32_t)(mt * (16 * 144) + ks * 32);
                    asm volatile(
                        "ldmatrix.sync.aligned.m8n8.x4.shared.b16 {%0,%1,%2,%3}, [%4];"
                        : "=r"(a0), "=r"(a1), "=r"(a2), "=r"(a3) : "r"(addr));
                    #pragma unroll
                    for (int nt = 0; nt < 8; nt++)
                        mma16816(acc[mt][nt], a0, a1, a2, a3, bb[nt].x, bb[nt].y);
                }
            }
        }
    }
}

// Column partial sums / sumsq from fragments into per-warp SMEM slots.
static __device__ __forceinline__ void reduce_stats(
    float acc[2][8][4], float* psum, float* psq, int w, int lane)
{
    const int rg = w >> 3, cg = w & 7;
    #pragma unroll
    for (int nt = 0; nt < 8; nt++) {
        float s0 = acc[0][nt][0] + acc[0][nt][2] + acc[1][nt][0] + acc[1][nt][2];
        float s1 = acc[0][nt][1] + acc[0][nt][3] + acc[1][nt][1] + acc[1][nt][3];
        float q0 = acc[0][nt][0] * acc[0][nt][0] + acc[0][nt][2] * acc[0][nt][2]
                 + acc[1][nt][0] * acc[1][nt][0] + acc[1][nt][2] * acc[1][nt][2];
        float q1 = acc[0][nt][1] * acc[0][nt][1] + acc[0][nt][3] * acc[0][nt][3]
                 + acc[1][nt][1] * acc[1][nt][1] + acc[1][nt][3] * acc[1][nt][3];
        #pragma unroll
        for (int d = 4; d < 32; d <<= 1) {
            s0 += __shfl_xor_sync(0xFFFFFFFFu, s0, d);
            s1 += __shfl_xor_sync(0xFFFFFFFFu, s1, d);
            q0 += __shfl_xor_sync(0xFFFFFFFFu, q0, d);
            q1 += __shfl_xor_sync(0xFFFFFFFFu, q1, d);
        }
        if (lane < 4) {
            int c0 = cg * 64 + nt * 8 + 2 * lane;
            psum[rg * 512 + c0]     += s0;
            psum[rg * 512 + c0 + 1] += s1;
            psq [rg * 512 + c0]     += q0;
            psq [rg * 512 + c0 + 1] += q1;
        }
    }
}

// Warp-per-4-rows sparsemax over 512 cols held row-major in SMEM.
template <bool PRE_NORMALIZED>
static __device__ __forceinline__ void sparsemax_rows(
    const float* __restrict__ cb, const float* __restrict__ scale,
    const float* __restrict__ shift, const float* __restrict__ priors,
    float* __restrict__ out, int grow_base, int w, int lane)
{
    #pragma unroll 1
    for (int q = 0; q < 4; q++) {
        const int lr = w * 4 + q;
        const int grow = grow_base + lr;
        const float* prow = priors + (size_t)grow * D_G;
        float v[16];
        float vmax = -3.4e38f;
        #pragma unroll
        for (int t = 0; t < 16; t++) {
            int c = lane + 32 * t;
            float z = cb[lr * CPITCH + c];
            if (!PRE_NORMALIZED) z = fmaf(z, scale[c], shift[c]);
            v[t] = z * prow[c];
            vmax = fmaxf(vmax, v[t]);
        }
        #pragma unroll
        for (int d = 16; d > 0; d >>= 1)
            vmax = fmaxf(vmax, __shfl_xor_sync(0xFFFFFFFFu, vmax, d));

        // Newton on g(tau) = sum(relu(v - tau)) - 1 : convex, piecewise linear,
        // monotone iterates from tau0 = vmax - 1 (g(tau0) >= 0), exact fixed pt.
        float tau = vmax - 1.0f;
        #pragma unroll 1
        for (int it = 0; it < 32; it++) {
            float s = 0.f, k = 0.f;
            #pragma unroll
            for (int t = 0; t < 16; t++)
                if (v[t] > tau) { s += v[t]; k += 1.0f; }
            #pragma unroll
            for (int d = 16; d > 0; d >>= 1) {
                s += __shfl_xor_sync(0xFFFFFFFFu, s, d);
                k += __shfl_xor_sync(0xFFFFFFFFu, k, d);
            }
            if (k < 0.5f) break;
            float tn = (s - 1.0f) / k;
            if (tn == tau) break;
            tau = tn;
        }
        float* orow = out + (size_t)grow * D_G;
        #pragma unroll
        for (int t = 0; t < 16; t++) {
            int c = lane + 32 * t;
            orow[c] = fmaxf(v[t] - tau, 0.0f);
        }
    }
}

// ===================== fused kernel ==========================
__global__ void __launch_bounds__(512, 1)
attentive_fused_kernel(const float* __restrict__ priors,
                       const float* __restrict__ feat,
                       const float* __restrict__ gamma,
                       const float* __restrict__ beta,
                       float* __restrict__ out)
{
    extern __shared__ char smem[];
    const uint32_t sb = smem_u32(smem);
    const int tid = threadIdx.x;
    const int w = tid >> 5, lane = tid & 31;
    const int row0 = blockIdx.x * VBS;

    float* psum  = (float*)(smem + OFF_PSUM);
    float* psq   = (float*)(smem + OFF_PSQ);
    float* scale = (float*)(smem + OFF_SCALE);
    float* shift = (float*)(smem + OFF_SHIFT);
    float* cb    = (float*)(smem + OFF_CBUF);

    // zero column partials
    psum[tid] = 0.f; psum[512 + tid] = 0.f;
    psq [tid] = 0.f; psq [512 + tid] = 0.f;

    float acc[2][8][4];

    // ---------- half 0: rows row0 .. row0+63 ----------
    #pragma unroll
    for (int mt = 0; mt < 2; mt++)
        #pragma unroll
        for (int nt = 0; nt < 8; nt++)
            #pragma unroll
            for (int e = 0; e < 4; e++) acc[mt][nt][e] = 0.f;
    gemm_half(feat, row0, smem, sb, tid, w, lane, acc);
    reduce_stats(acc, psum, psq, w, lane);

    // spill raw C (rows 0-63) to SMEM row-major
    {
        const int rg = w >> 3, cg = w & 7;
        #pragma unroll
        for (int mt = 0; mt < 2; mt++) {
            int row = rg * 32 + mt * 16 + (lane >> 2);
            #pragma unroll
            for (int nt = 0; nt < 8; nt++) {
                int c = cg * 64 + nt * 8 + 2 * (lane & 3);
                *(float2*)(cb + row * CPITCH + c) =
                    make_float2(acc[mt][nt][0], acc[mt][nt][1]);
                *(float2*)(cb + (row + 8) * CPITCH + c) =
                    make_float2(acc[mt][nt][2], acc[mt][nt][3]);
            }
        }
    }

    // ---------- half 1: rows row0+64 .. row0+127 ----------
    #pragma unroll
    for (int mt = 0; mt < 2; mt++)
        #pragma unroll
        for (int nt = 0; nt < 8; nt++)
            #pragma unroll
            for (int e = 0; e < 4; e++) acc[mt][nt][e] = 0.f;
    gemm_half(feat, row0 + 64, smem, sb, tid, w, lane, acc);
    reduce_stats(acc, psum, psq, w, lane);
    __syncthreads();

    // ---------- finalize GBN scale/shift (one thread per column) ----------
    {
        int c = tid;
        float m  = (psum[c] + psum[512 + c]) * (1.0f / 128.0f);
        float ms = (psq [c] + psq [512 + c]) * (1.0f / 128.0f);
        float var = ms - m * m;
        float sc = gamma[c] * rsqrtf(var + 1e-5f);
        scale[c] = sc;
        shift[c] = beta[c] - m * sc;
    }
    __syncthreads();

    // ---------- sparsemax rows 0-63 (normalize on the fly) ----------
    sparsemax_rows<false>(cb, scale, shift, priors, out, row0, w, lane);
    __syncthreads();

    // ---------- write normalized half-1 regs into SMEM ----------
    {
        const int rg = w >> 3, cg = w & 7;
        #pragma unroll
        for (int mt = 0; mt < 2; mt++) {
            int row = rg * 32 + mt * 16 + (lane >> 2);
            #pragma unroll
            for (int nt = 0; nt < 8; nt++) {
                int c = cg * 64 + nt * 8 + 2 * (lane & 3);
                float z0 = fmaf(acc[mt][nt][0], scale[c],     shift[c]);
                float z1 = fmaf(acc[mt][nt][1], scale[c + 1], shift[c + 1]);
                float z2 = fmaf(acc[mt][nt][2], scale[c],     shift[c]);
                float z3 = fmaf(acc[mt][nt][3], scale[c + 1], shift[c + 1]);
                *(float2*)(cb + row * CPITCH + c)       = make_float2(z0, z1);
                *(float2*)(cb + (row + 8) * CPITCH + c) = make_float2(z2, z3);
            }
        }
    }
    __syncthreads();

    // ---------- sparsemax rows 64-127 ----------
    sparsemax_rows<true>(cb, scale, shift, priors, out, row0 + 64, w, lane);
}

// ===================== launch ================================
extern "C" void kernel_launch(void* const* d_in, const int* in_sizes, int n_in,
                              void* d_out, int out_size) {
    (void)in_sizes; (void)n_in; (void)out_size;
    const float* priors = (const float*)d_in[0];   // [65536, 512]
    const float* feat   = (const float*)d_in[1];   // [65536, 256]
    const float* W      = (const float*)d_in[2];   // [512, 256]
    const float* gamma  = (const float*)d_in[3];   // [512]
    const float* beta   = (const float*)d_in[4];   // [512]
    float* out = (float*)d_out;                    // [65536, 512]

    cudaFuncSetAttribute(attentive_fused_kernel,
                         cudaFuncAttributeMaxDynamicSharedMemorySize, DYN_SMEM);

    prep_w_kernel<<<256, 256>>>(W);
    attentive_fused_kernel<<<512, 512, DYN_SMEM>>>(priors, feat, gamma, beta, out);
}

// round 15
// speedup vs baseline: 1.2175x; 1.2175x over previous
#include <cuda_runtime.h>
#include <cuda_bf16.h>
#include <stdint.h>

// ===================== problem constants =====================
#define D_IN 256
#define D_G  512
#define VBS  128

// ===================== SMEM layout (bytes) ===================
// stats: psum f32[512] (-> scale), psq f32[512] (-> shift)
#define OFF_PSUM  0               // 2048
#define OFF_PSQ   2048            // 2048
#define OFF_A     4096            // 2 slots x 10240 (64 rows x 80B pitch, hi+lo)
#define A_SLOT    10240
#define A_LO      5120
#define OFF_B     24576           // 2 slots x 32768 (hi 16K + lo 16K), fragment order
#define B_SLOT    32768
#define OFF_CBUF  90112           // f32[64][520] = 133120 -> end 223232
#define DYN_SMEM  223232
#define CPITCH    520

// ===================== W fragment scratch (kt-major) =========
// uint2 index = (kt*64 + nt_glob)*32 + lane   (kt 0..15, nt_glob 0..63)
//   n  = nt_glob*8 + (lane>>2)
//   k0 = kt*16 + (lane&3)*2
//   .x = pack(W[n][k0],   W[n][k0+1])
//   .y = pack(W[n][k0+8], W[n][k0+9])
__device__ uint2 g_Bhi2[16 * 64 * 32];
__device__ uint2 g_Blo2[16 * 64 * 32];

static __device__ __forceinline__ uint32_t packbf(float a, float b) {
    union { __nv_bfloat16 h[2]; uint32_t u; } U;
    U.h[0] = __float2bfloat16(a);
    U.h[1] = __float2bfloat16(b);
    return U.u;
}

__global__ void prep_w_kernel(const float* __restrict__ W) {
    int idx  = blockIdx.x * 256 + threadIdx.x;   // 0..32767
    int lane = idx & 31;
    int nt   = (idx >> 5) & 63;
    int kt   = idx >> 11;
    int n  = nt * 8 + (lane >> 2);
    int k0 = kt * 16 + (lane & 3) * 2;
    float w00 = W[n * D_IN + k0],     w01 = W[n * D_IN + k0 + 1];
    float w10 = W[n * D_IN + k0 + 8], w11 = W[n * D_IN + k0 + 9];
    __nv_bfloat16 h00 = __float2bfloat16(w00), h01 = __float2bfloat16(w01);
    __nv_bfloat16 h10 = __float2bfloat16(w10), h11 = __float2bfloat16(w11);
    uint2 hi, lo;
    { union { __nv_bfloat16 h[2]; uint32_t u; } U;
      U.h[0] = h00; U.h[1] = h01; hi.x = U.u;
      U.h[0] = h10; U.h[1] = h11; hi.y = U.u; }
    lo.x = packbf(w00 - __bfloat162float(h00), w01 - __bfloat162float(h01));
    lo.y = packbf(w10 - __bfloat162float(h10), w11 - __bfloat162float(h11));
    g_Bhi2[idx] = hi;
    g_Blo2[idx] = lo;
}

// ===================== device helpers ========================
static __device__ __forceinline__ uint32_t smem_u32(const void* p) {
    uint32_t a;
    asm("{ .reg .u64 t; cvta.to.shared.u64 t, %1; cvt.u32.u64 %0, t; }"
        : "=r"(a) : "l"(p));
    return a;
}

#define CP_ASYNC16(dst, src) \
    asm volatile("cp.async.cg.shared.global [%0], [%1], 16;" \
                 :: "r"(dst), "l"(src) : "memory")
#define CP_COMMIT() asm volatile("cp.async.commit_group;" ::: "memory")
#define CP_WAIT0()  asm volatile("cp.async.wait_group 0;" ::: "memory")

static __device__ __forceinline__ void mma16816(float d[4],
                                                uint32_t a0, uint32_t a1,
                                                uint32_t a2, uint32_t a3,
                                                uint32_t b0, uint32_t b1) {
    asm volatile(
        "mma.sync.aligned.m16n8k16.row.col.f32.bf16.bf16.f32 "
        "{%0,%1,%2,%3}, {%4,%5,%6,%7}, {%8,%9}, {%0,%1,%2,%3};"
        : "+f"(d[0]), "+f"(d[1]), "+f"(d[2]), "+f"(d[3])
        : "r"(a0), "r"(a1), "r"(a2), "r"(a3), "r"(b0), "r"(b1));
}

static __device__ __forceinline__ void ldmx4(uint32_t r[4], uint32_t addr) {
    asm volatile("ldmatrix.sync.aligned.m8n8.x4.shared.b16 {%0,%1,%2,%3}, [%4];"
                 : "=r"(r[0]), "=r"(r[1]), "=r"(r[2]), "=r"(r[3]) : "r"(addr));
}

// stage A chunk kc (64 rows x 32 K) into A slot, hi/lo bf16, pitch 80 B
static __device__ __forceinline__ void stageA(
    const float* __restrict__ feat, int grow0, char* smem, int tid, int kc, int slot)
{
    int r  = tid >> 3;          // 0..63
    int c4 = (tid & 7) * 4;     // 0..28
    float4 f = *(const float4*)(feat + (size_t)(grow0 + r) * D_IN + kc * 32 + c4);
    uint2 hi, lo;
    hi.x = packbf(f.x, f.y);  hi.y = packbf(f.z, f.w);
    __nv_bfloat16 hx = __float2bfloat16(f.x), hy = __float2bfloat16(f.y);
    __nv_bfloat16 hz = __float2bfloat16(f.z), hw = __float2bfloat16(f.w);
    lo.x = packbf(f.x - __bfloat162float(hx), f.y - __bfloat162float(hy));
    lo.y = packbf(f.z - __bfloat162float(hz), f.w - __bfloat162float(hw));
    char* base = smem + OFF_A + slot * A_SLOT + r * 80 + c4 * 2;
    *(uint2*)(base)        = hi;
    *(uint2*)(base + A_LO) = lo;
}

// issue cp.async for B(kt) into slot: 32 KB (hi 16K + lo 16K), 4x16B per thread
static __device__ __forceinline__ void issueB(uint32_t sb, int tid, int kt, int slot) {
    const char* sh = (const char*)g_Bhi2 + (size_t)kt * 16384;
    const char* sl = (const char*)g_Blo2 + (size_t)kt * 16384;
    uint32_t dh = sb + OFF_B + slot * B_SLOT;
    uint32_t dl = dh + 16384;
    CP_ASYNC16(dh + tid * 16,        sh + tid * 16);
    CP_ASYNC16(dh + 8192 + tid * 16, sh + 8192 + tid * 16);
    CP_ASYNC16(dl + tid * 16,        sl + tid * 16);
    CP_ASYNC16(dl + 8192 + tid * 16, sl + 8192 + tid * 16);
    CP_COMMIT();
}

// GEMM for one 64-row half; acc[mt][nt][4]: warp tile rows rg*32.., cols cg*64..
static __device__ __forceinline__ void gemm_half(
    const float* __restrict__ feat, int grow0, char* smem, uint32_t sb,
    int tid, int w, int lane, float acc[2][8][4])
{
    const int rg = w >> 3, cg = w & 7;
    const uint32_t a_frag = (uint32_t)((rg * 32 + (lane & 15)) * 80 + (lane >> 4) * 16);
    const uint32_t b_frag = (uint32_t)(((cg * 8) * 32 + lane) * 8);

    stageA(feat, grow0, smem, tid, 0, 0);
    issueB(sb, tid, 0, 0);

    #pragma unroll 1
    for (int kt = 0; kt < 16; kt++) {
        CP_WAIT0();          // B(kt) copies done (this thread)
        __syncthreads();     // all threads' copies visible; prev slot reads done
        if (kt + 1 < 16) issueB(sb, tid, kt + 1, (kt + 1) & 1);
        if ((kt & 1) == 0 && kt + 2 < 16)
            stageA(feat, grow0, smem, tid, (kt >> 1) + 1, ((kt >> 1) + 1) & 1);

        const uint32_t aslot = sb + OFF_A + (((uint32_t)kt >> 1) & 1) * A_SLOT;
        const char*    bslot = smem + OFF_B + (kt & 1) * B_SLOT;
        uint32_t ah0 = aslot + a_frag + (kt & 1) * 32;
        uint32_t al0 = ah0 + A_LO;

        uint32_t ah[2][4], al[2][4];
        ldmx4(ah[0], ah0);
        ldmx4(ah[1], ah0 + 16 * 80);
        ldmx4(al[0], al0);
        ldmx4(al[1], al0 + 16 * 80);

        uint2 bb[8];
        // ---- Bh: passes Ah*Bh and Al*Bh ----
        #pragma unroll
        for (int nt = 0; nt < 8; nt++)
            bb[nt] = *(const uint2*)(bslot + b_frag + nt * 256);
        #pragma unroll
        for (int nt = 0; nt < 8; nt++) {
            mma16816(acc[0][nt], ah[0][0], ah[0][1], ah[0][2], ah[0][3], bb[nt].x, bb[nt].y);
            mma16816(acc[1][nt], ah[1][0], ah[1][1], ah[1][2], ah[1][3], bb[nt].x, bb[nt].y);
        }
        #pragma unroll
        for (int nt = 0; nt < 8; nt++) {
            mma16816(acc[0][nt], al[0][0], al[0][1], al[0][2], al[0][3], bb[nt].x, bb[nt].y);
            mma16816(acc[1][nt], al[1][0], al[1][1], al[1][2], al[1][3], bb[nt].x, bb[nt].y);
        }
        // ---- Bl: pass Ah*Bl ----
        #pragma unroll
        for (int nt = 0; nt < 8; nt++)
            bb[nt] = *(const uint2*)(bslot + 16384 + b_frag + nt * 256);
        #pragma unroll
        for (int nt = 0; nt < 8; nt++) {
            mma16816(acc[0][nt], ah[0][0], ah[0][1], ah[0][2], ah[0][3], bb[nt].x, bb[nt].y);
            mma16816(acc[1][nt], ah[1][0], ah[1][1], ah[1][2], ah[1][3], bb[nt].x, bb[nt].y);
        }
    }
}

// Column partial sums/sumsq via smem atomicAdd (degree-2 contention).
static __device__ __forceinline__ void reduce_stats(
    float acc[2][8][4], float* psum, float* psq, int w, int lane)
{
    const int cg = w & 7;
    #pragma unroll
    for (int nt = 0; nt < 8; nt++) {
        float s0 = acc[0][nt][0] + acc[0][nt][2] + acc[1][nt][0] + acc[1][nt][2];
        float s1 = acc[0][nt][1] + acc[0][nt][3] + acc[1][nt][1] + acc[1][nt][3];
        float q0 = acc[0][nt][0] * acc[0][nt][0] + acc[0][nt][2] * acc[0][nt][2]
                 + acc[1][nt][0] * acc[1][nt][0] + acc[1][nt][2] * acc[1][nt][2];
        float q1 = acc[0][nt][1] * acc[0][nt][1] + acc[0][nt][3] * acc[0][nt][3]
                 + acc[1][nt][1] * acc[1][nt][1] + acc[1][nt][3] * acc[1][nt][3];
        #pragma unroll
        for (int d = 4; d < 32; d <<= 1) {
            s0 += __shfl_xor_sync(0xFFFFFFFFu, s0, d);
            s1 += __shfl_xor_sync(0xFFFFFFFFu, s1, d);
            q0 += __shfl_xor_sync(0xFFFFFFFFu, q0, d);
            q1 += __shfl_xor_sync(0xFFFFFFFFu, q1, d);
        }
        if (lane < 4) {
            int c0 = cg * 64 + nt * 8 + 2 * lane;
            atomicAdd(&psum[c0],     s0);
            atomicAdd(&psum[c0 + 1], s1);
            atomicAdd(&psq[c0],      q0);
            atomicAdd(&psq[c0 + 1],  q1);
        }
    }
}

// Warp-per-4-rows sparsemax over 512 cols held row-major in SMEM.
template <bool PRE_NORMALIZED>
static __device__ __forceinline__ void sparsemax_rows(
    const float* __restrict__ cb, const float* __restrict__ scale,
    const float* __restrict__ shift, const float* __restrict__ priors,
    float* __restrict__ out, int grow_base, int w, int lane)
{
    #pragma unroll 1
    for (int q = 0; q < 4; q++) {
        const int lr = w * 4 + q;
        const int grow = grow_base + lr;
        const float* prow = priors + (size_t)grow * D_G;
        float v[16];
        float vmax = -3.4e38f;
        #pragma unroll
        for (int t = 0; t < 16; t++) {
            int c = lane + 32 * t;
            float z = cb[lr * CPITCH + c];
            if (!PRE_NORMALIZED) z = fmaf(z, scale[c], shift[c]);
            v[t] = z * prow[c];
            vmax = fmaxf(vmax, v[t]);
        }
        #pragma unroll
        for (int d = 16; d > 0; d >>= 1)
            vmax = fmaxf(vmax, __shfl_xor_sync(0xFFFFFFFFu, vmax, d));

        // Newton on g(tau) = sum(relu(v - tau)) - 1 : convex, piecewise linear
        float tau = vmax - 1.0f;
        #pragma unroll 1
        for (int it = 0; it < 32; it++) {
            float s = 0.f, k = 0.f;
            #pragma unroll
            for (int t = 0; t < 16; t++)
                if (v[t] > tau) { s += v[t]; k += 1.0f; }
            #pragma unroll
            for (int d = 16; d > 0; d >>= 1) {
                s += __shfl_xor_sync(0xFFFFFFFFu, s, d);
                k += __shfl_xor_sync(0xFFFFFFFFu, k, d);
            }
            if (k < 0.5f) break;
            float tn = (s - 1.0f) / k;
            if (tn == tau) break;
            tau = tn;
        }
        float* orow = out + (size_t)grow * D_G;
        #pragma unroll
        for (int t = 0; t < 16; t++) {
            int c = lane + 32 * t;
            orow[c] = fmaxf(v[t] - tau, 0.0f);
        }
    }
}

// ===================== fused kernel ==========================
__global__ void __launch_bounds__(512, 1)
attentive_fused_kernel(const float* __restrict__ priors,
                       const float* __restrict__ feat,
                       const float* __restrict__ gamma,
                       const float* __restrict__ beta,
                       float* __restrict__ out)
{
    extern __shared__ char smem[];
    const uint32_t sb = smem_u32(smem);
    const int tid = threadIdx.x;
    const int w = tid >> 5, lane = tid & 31;
    const int row0 = blockIdx.x * VBS;

    float* psum = (float*)(smem + OFF_PSUM);
    float* psq  = (float*)(smem + OFF_PSQ);
    float* cb   = (float*)(smem + OFF_CBUF);

    psum[tid] = 0.f;
    psq[tid]  = 0.f;
    __syncthreads();

    float acc[2][8][4];

    // ---------- half 0: rows row0 .. row0+63 ----------
    #pragma unroll
    for (int mt = 0; mt < 2; mt++)
        #pragma unroll
        for (int nt = 0; nt < 8; nt++)
            #pragma unroll
            for (int e = 0; e < 4; e++) acc[mt][nt][e] = 0.f;
    gemm_half(feat, row0, smem, sb, tid, w, lane, acc);
    reduce_stats(acc, psum, psq, w, lane);

    // spill raw C (rows 0-63) to SMEM row-major
    {
        const int rg = w >> 3, cg = w & 7;
        #pragma unroll
        for (int mt = 0; mt < 2; mt++) {
            int row = rg * 32 + mt * 16 + (lane >> 2);
            #pragma unroll
            for (int nt = 0; nt < 8; nt++) {
                int c = cg * 64 + nt * 8 + 2 * (lane & 3);
                *(float2*)(cb + row * CPITCH + c) =
                    make_float2(acc[mt][nt][0], acc[mt][nt][1]);
                *(float2*)(cb + (row + 8) * CPITCH + c) =
                    make_float2(acc[mt][nt][2], acc[mt][nt][3]);
            }
        }
    }

    // ---------- half 1: rows row0+64 .. row0+127 ----------
    #pragma unroll
    for (int mt = 0; mt < 2; mt++)
        #pragma unroll
        for (int nt = 0; nt < 8; nt++)
            #pragma unroll
            for (int e = 0; e < 4; e++) acc[mt][nt][e] = 0.f;
    gemm_half(feat, row0 + 64, smem, sb, tid, w, lane, acc);
    reduce_stats(acc, psum, psq, w, lane);
    __syncthreads();

    // ---------- finalize GBN: scale->psum, shift->psq (in place) ----------
    {
        int c = tid;
        float m  = psum[c] * (1.0f / 128.0f);
        float ms = psq[c]  * (1.0f / 128.0f);
        float var = ms - m * m;
        float sc = gamma[c] * rsqrtf(var + 1e-5f);
        psum[c] = sc;                  // scale
        psq[c]  = beta[c] - m * sc;    // shift
    }
    __syncthreads();

    // ---------- sparsemax rows 0-63 (normalize on the fly) ----------
    sparsemax_rows<false>(cb, psum, psq, priors, out, row0, w, lane);
    __syncthreads();

    // ---------- write normalized half-1 regs into SMEM ----------
    {
        const int rg = w >> 3, cg = w & 7;
        #pragma unroll
        for (int mt = 0; mt < 2; mt++) {
            int row = rg * 32 + mt * 16 + (lane >> 2);
            #pragma unroll
            for (int nt = 0; nt < 8; nt++) {
                int c = cg * 64 + nt * 8 + 2 * (lane & 3);
                float z0 = fmaf(acc[mt][nt][0], psum[c],     psq[c]);
                float z1 = fmaf(acc[mt][nt][1], psum[c + 1], psq[c + 1]);
                float z2 = fmaf(acc[mt][nt][2], psum[c],     psq[c]);
                float z3 = fmaf(acc[mt][nt][3], psum[c + 1], psq[c + 1]);
                *(float2*)(cb + row * CPITCH + c)       = make_float2(z0, z1);
                *(float2*)(cb + (row + 8) * CPITCH + c) = make_float2(z2, z3);
            }
        }
    }
    __syncthreads();

    // ---------- sparsemax rows 64-127 ----------
    sparsemax_rows<true>(cb, psum, psq, priors, out, row0 + 64, w, lane);
}

// ===================== launch ================================
extern "C" void kernel_launch(void* const* d_in, const int* in_sizes, int n_in,
                              void* d_out, int out_size) {
    (void)in_sizes; (void)n_in; (void)out_size;
    const float* priors = (const float*)d_in[0];   // [65536, 512]
    const float* feat   = (const float*)d_in[1];   // [65536, 256]
    const float* W      = (const float*)d_in[2];   // [512, 256]
    const float* gamma  = (const float*)d_in[3];   // [512]
    const float* beta   = (const float*)d_in[4];   // [512]
    float* out = (float*)d_out;                    // [65536, 512]

    cudaFuncSetAttribute(attentive_fused_kernel,
                         cudaFuncAttributeMaxDynamicSharedMemorySize, DYN_SMEM);

    prep_w_kernel<<<128, 256>>>(W);
    attentive_fused_kernel<<<512, 512, DYN_SMEM>>>(priors, feat, gamma, beta, out);
}